// round 4
// baseline (speedup 1.0000x reference)
#include <cuda_runtime.h>

#define Nn 100000
#define Ee 3200000
#define ET (Ee + Nn)

// ---- scratch (static __device__ globals; no allocation allowed) ----
__device__ int    g_off[Nn + 1];
__device__ int    g_cur[Nn];
__device__ int    g_csr[ET];
__device__ float  g_h2[Nn * 16];
__device__ float2 g_as2[Nn];
__device__ float2 g_ad2[Nn];
__device__ float  g_pool[16];

__global__ void k_init() {
    int i = blockIdx.x * blockDim.x + threadIdx.x;
    if (i < Nn) g_cur[i] = 1;          // degree starts at 1 (self loop)
    if (i < 16) g_pool[i] = 0.f;
}

__global__ void k_hist(const int* __restrict__ dst) {
    int e = blockIdx.x * blockDim.x + threadIdx.x;
    if (e < Ee) atomicAdd(&g_cur[dst[e]], 1);
}

// single-block exclusive scan of degrees -> offsets
__global__ void k_scan() {
    __shared__ int sm[1024];
    int t = threadIdx.x;
    int beg = t * 98;
    int end = beg + 98 < Nn ? beg + 98 : Nn;
    int s = 0;
    for (int j = beg; j < end; j++) s += g_cur[j];
    sm[t] = s;
    __syncthreads();
    for (int o = 1; o < 1024; o <<= 1) {
        int v = (t >= o) ? sm[t - o] : 0;
        __syncthreads();
        sm[t] += v;
        __syncthreads();
    }
    int run = sm[t] - s;  // exclusive base
    for (int j = beg; j < end; j++) { g_off[j] = run; run += g_cur[j]; }
    if (t == 1023) g_off[Nn] = sm[1023];
}

// place self-loop at slot off[i], cursor starts after it
__global__ void k_place() {
    int i = blockIdx.x * blockDim.x + threadIdx.x;
    if (i < Nn) {
        int o = g_off[i];
        g_csr[o] = i;
        g_cur[i] = o + 1;
    }
}

__global__ void k_scatter(const int* __restrict__ src, const int* __restrict__ dst) {
    int e = blockIdx.x * blockDim.x + threadIdx.x;
    if (e < Ee) {
        int p = atomicAdd(&g_cur[dst[e]], 1);
        g_csr[p] = src[e];
    }
}

// Layer 1 (rank-1 GAT) + node-local layer-2 projection.
// Warp per node. Produces g_h2 (h2pre, 16/node), g_as2/g_ad2 (layer-2 attn scalars).
__global__ void k_layer1(const float* __restrict__ x,
                         const float* __restrict__ W1, const float* __restrict__ as1,
                         const float* __restrict__ ad1, const float* __restrict__ b1,
                         const float* __restrict__ W2, const float* __restrict__ as2,
                         const float* __restrict__ ad2) {
    __shared__ float W1s[64], b1s[64], W2s[1024], s1s[4], d1s[4], as2s[16], ad2s[16];
    int tid = threadIdx.x;
    if (tid < 64) { W1s[tid] = W1[tid]; b1s[tid] = b1[tid]; }
    for (int j = tid; j < 1024; j += blockDim.x) W2s[j] = W2[j];
    if (tid < 16) { as2s[tid] = as2[tid]; ad2s[tid] = ad2[tid]; }
    if (tid < 8) {
        int h = tid & 3;
        const float* a = (tid < 4) ? as1 : ad1;
        float s = 0.f;
        #pragma unroll
        for (int c = 0; c < 16; c++) s += W1[h * 16 + c] * a[h * 16 + c];
        if (tid < 4) s1s[h] = s; else d1s[h] = s;
    }
    __syncthreads();

    int i = blockIdx.x * (blockDim.x >> 5) + (tid >> 5);
    if (i >= Nn) return;
    int lane = tid & 31;

    float xi = x[i];
    int lo = g_off[i], hi = g_off[i + 1];
    float s10 = s1s[0], s11 = s1s[1], s12 = s1s[2], s13 = s1s[3];
    float xd0 = xi * d1s[0], xd1 = xi * d1s[1], xd2 = xi * d1s[2], xd3 = xi * d1s[3];
    float n0 = 0.f, n1 = 0.f, n2 = 0.f, n3 = 0.f;
    float d0 = 0.f, d1v = 0.f, d2 = 0.f, d3 = 0.f;

    for (int p = lo + lane; p < hi; p += 32) {
        int s = g_csr[p];
        float xs = __ldg(&x[s]);
        float e0 = xs * s10 + xd0; e0 = e0 > 0.f ? e0 : 0.2f * e0; float w0 = __expf(e0);
        float e1 = xs * s11 + xd1; e1 = e1 > 0.f ? e1 : 0.2f * e1; float w1 = __expf(e1);
        float e2 = xs * s12 + xd2; e2 = e2 > 0.f ? e2 : 0.2f * e2; float w2 = __expf(e2);
        float e3 = xs * s13 + xd3; e3 = e3 > 0.f ? e3 : 0.2f * e3; float w3 = __expf(e3);
        d0 += w0; d1v += w1; d2 += w2; d3 += w3;
        n0 = fmaf(w0, xs, n0); n1 = fmaf(w1, xs, n1);
        n2 = fmaf(w2, xs, n2); n3 = fmaf(w3, xs, n3);
    }
    #pragma unroll
    for (int o = 16; o > 0; o >>= 1) {
        n0 += __shfl_xor_sync(~0u, n0, o); n1 += __shfl_xor_sync(~0u, n1, o);
        n2 += __shfl_xor_sync(~0u, n2, o); n3 += __shfl_xor_sync(~0u, n3, o);
        d0 += __shfl_xor_sync(~0u, d0, o); d1v += __shfl_xor_sync(~0u, d1v, o);
        d2 += __shfl_xor_sync(~0u, d2, o); d3 += __shfl_xor_sync(~0u, d3, o);
    }
    float S0 = n0 / (d0 + 1e-16f), S1 = n1 / (d1v + 1e-16f);
    float S2 = n2 / (d2 + 1e-16f), S3 = n3 / (d3 + 1e-16f);

    // h2pre[c] = sum_j relu(W1[j]*S[j>>4] + b1[j]) * W2[j][c]
    // lane handles c = lane&15, half of j-range per lane, then xor-16 combine.
    int c = lane & 15;
    int jb = (lane >> 4) * 32;
    float SA = (lane < 16) ? S0 : S2;
    float SB = (lane < 16) ? S1 : S3;
    float acc = 0.f;
    #pragma unroll
    for (int jj = 0; jj < 32; jj++) {
        float Sv = (jj < 16) ? SA : SB;
        int j = jb + jj;
        float o1 = fmaf(W1s[j], Sv, b1s[j]);
        o1 = o1 > 0.f ? o1 : 0.f;
        acc = fmaf(o1, W2s[j * 16 + c], acc);
    }
    acc += __shfl_xor_sync(~0u, acc, 16);  // all lanes: full h2pre[c]

    if (lane < 16) g_h2[i * 16 + lane] = acc;

    // layer-2 attention scalars: per-head (8-wide) dot products
    float ps = acc * as2s[c], pd = acc * ad2s[c];
    #pragma unroll
    for (int o = 4; o > 0; o >>= 1) {
        ps += __shfl_xor_sync(~0u, ps, o);
        pd += __shfl_xor_sync(~0u, pd, o);
    }
    float ps0 = __shfl_sync(~0u, ps, 0), ps1 = __shfl_sync(~0u, ps, 8);
    float pd0 = __shfl_sync(~0u, pd, 0), pd1 = __shfl_sync(~0u, pd, 8);
    if (lane == 0) {
        g_as2[i] = make_float2(ps0, ps1);
        g_ad2[i] = make_float2(pd0, pd1);
    }
}

// Layer 2: warp per node, lane per edge, register accumulation, fused mean-pool.
__global__ void k_layer2(const float* __restrict__ b2) {
    __shared__ float pool_s[16];
    int tid = threadIdx.x;
    if (tid < 16) pool_s[tid] = 0.f;
    __syncthreads();

    int i = blockIdx.x * (blockDim.x >> 5) + (tid >> 5);
    int lane = tid & 31;
    if (i < Nn) {
        float2 ad = g_ad2[i];
        int lo = g_off[i], hi = g_off[i + 1];
        float den0 = 0.f, den1 = 0.f;
        float acc[16];
        #pragma unroll
        for (int c = 0; c < 16; c++) acc[c] = 0.f;

        for (int p = lo + lane; p < hi; p += 32) {
            int s = g_csr[p];
            float2 as = __ldg(&g_as2[s]);
            float e0 = as.x + ad.x; e0 = e0 > 0.f ? e0 : 0.2f * e0; float w0 = __expf(e0);
            float e1 = as.y + ad.y; e1 = e1 > 0.f ? e1 : 0.2f * e1; float w1 = __expf(e1);
            den0 += w0; den1 += w1;
            const float4* hp = (const float4*)(g_h2 + s * 16);
            float4 v0 = __ldg(hp), v1 = __ldg(hp + 1), v2 = __ldg(hp + 2), v3 = __ldg(hp + 3);
            acc[0]  = fmaf(w0, v0.x, acc[0]);  acc[1]  = fmaf(w0, v0.y, acc[1]);
            acc[2]  = fmaf(w0, v0.z, acc[2]);  acc[3]  = fmaf(w0, v0.w, acc[3]);
            acc[4]  = fmaf(w0, v1.x, acc[4]);  acc[5]  = fmaf(w0, v1.y, acc[5]);
            acc[6]  = fmaf(w0, v1.z, acc[6]);  acc[7]  = fmaf(w0, v1.w, acc[7]);
            acc[8]  = fmaf(w1, v2.x, acc[8]);  acc[9]  = fmaf(w1, v2.y, acc[9]);
            acc[10] = fmaf(w1, v2.z, acc[10]); acc[11] = fmaf(w1, v2.w, acc[11]);
            acc[12] = fmaf(w1, v3.x, acc[12]); acc[13] = fmaf(w1, v3.y, acc[13]);
            acc[14] = fmaf(w1, v3.z, acc[14]); acc[15] = fmaf(w1, v3.w, acc[15]);
        }
        #pragma unroll
        for (int o = 16; o > 0; o >>= 1) {
            den0 += __shfl_xor_sync(~0u, den0, o);
            den1 += __shfl_xor_sync(~0u, den1, o);
            #pragma unroll
            for (int c = 0; c < 16; c++) acc[c] += __shfl_xor_sync(~0u, acc[c], o);
        }
        if (lane < 16) {
            float mya = 0.f;
            #pragma unroll
            for (int c = 0; c < 16; c++) if (lane == c) mya = acc[c];
            float d = (lane < 8) ? den0 : den1;
            float v = mya / (d + 1e-16f) + b2[lane];
            v = v > 0.f ? v : 0.f;                 // relu(out2)
            atomicAdd(&pool_s[lane], v);
        }
    }
    __syncthreads();
    if (tid < 16) atomicAdd(&g_pool[tid], pool_s[tid]);
}

// MLP head + sigmoid, single warp.
__global__ void k_head(const float* __restrict__ f1w, const float* __restrict__ f1b,
                       const float* __restrict__ f2w, const float* __restrict__ f2b,
                       float* __restrict__ out) {
    int lane = threadIdx.x;
    const float invN = 1.f / (float)Nn;
    float z1 = f1b[lane];
    #pragma unroll
    for (int c = 0; c < 16; c++)
        z1 = fmaf(g_pool[c] * invN, f1w[c * 32 + lane], z1);
    z1 = z1 > 0.f ? z1 : 0.f;
    float z2 = (lane < 10) ? f2b[lane] : 0.f;
    #pragma unroll
    for (int k = 0; k < 32; k++) {
        float zk = __shfl_sync(~0u, z1, k);
        if (lane < 10) z2 = fmaf(zk, f2w[k * 10 + lane], z2);
    }
    if (lane < 10) out[lane] = 1.f / (1.f + __expf(-z2));
}

extern "C" void kernel_launch(void* const* d_in, const int* in_sizes, int n_in,
                              void* d_out, int out_size) {
    const float* x   = (const float*)d_in[0];
    const int*   ei  = (const int*)  d_in[1];
    const float* W1  = (const float*)d_in[2];
    const float* as1 = (const float*)d_in[3];
    const float* ad1 = (const float*)d_in[4];
    const float* b1  = (const float*)d_in[5];
    const float* W2  = (const float*)d_in[6];
    const float* as2 = (const float*)d_in[7];
    const float* ad2 = (const float*)d_in[8];
    const float* b2  = (const float*)d_in[9];
    const float* f1w = (const float*)d_in[10];
    const float* f1b = (const float*)d_in[11];
    const float* f2w = (const float*)d_in[12];
    const float* f2b = (const float*)d_in[13];

    const int* src = ei;
    const int* dst = ei + Ee;

    k_init   <<<(Nn + 255) / 256, 256>>>();
    k_hist   <<<(Ee + 255) / 256, 256>>>(dst);
    k_scan   <<<1, 1024>>>();
    k_place  <<<(Nn + 255) / 256, 256>>>();
    k_scatter<<<(Ee + 255) / 256, 256>>>(src, dst);
    k_layer1 <<<(Nn + 7) / 8, 256>>>(x, W1, as1, ad1, b1, W2, as2, ad2);
    k_layer2 <<<(Nn + 7) / 8, 256>>>(b2);
    k_head   <<<1, 32>>>(f1w, f1b, f2w, f2b, (float*)d_out);
}

// round 5
// speedup vs baseline: 1.7071x; 1.7071x over previous
#include <cuda_runtime.h>

#define Nn 100000
#define Ee 3200000
#define ET (Ee + Nn)
#define NB 391            // ceil(Nn/256)
#define NBUCK 128

// ---- scratch (__device__ globals; zero-initialized at module load) ----
__device__ int    g_cur[Nn];        // invariant: ==0 at entry of every call (layer1 re-zeroes)
__device__ int    g_off[Nn + 1];
__device__ int    g_csr[ET];
__device__ int    g_bsum[NB];
__device__ int    g_bbase[NB];
__device__ float  g_h2[Nn * 16];
__device__ float2 g_as2[Nn];
__device__ float2 g_ad2[Nn];
__device__ float  g_poolB[NBUCK * 16];

// -------- histogram of dst degrees (g_cur starts at 0; self-loop added in scan) ----
__global__ void k_hist(const int4* __restrict__ dst4) {
    int e = blockIdx.x * blockDim.x + threadIdx.x;   // exactly Ee/4 threads
    int4 d = __ldg(&dst4[e]);
    atomicAdd(&g_cur[d.x], 1);
    atomicAdd(&g_cur[d.y], 1);
    atomicAdd(&g_cur[d.z], 1);
    atomicAdd(&g_cur[d.w], 1);
}

// -------- 3-phase full-chip scan of (deg+1) --------
__global__ void k_scan1() {
    __shared__ int sm[256];
    int t = threadIdx.x;
    int i = blockIdx.x * 256 + t;
    int v = (i < Nn) ? g_cur[i] + 1 : 0;
    sm[t] = v;
    __syncthreads();
    #pragma unroll
    for (int o = 128; o > 0; o >>= 1) {
        if (t < o) sm[t] += sm[t + o];
        __syncthreads();
    }
    if (t == 0) g_bsum[blockIdx.x] = sm[0];
}

__global__ void k_scan2() {
    __shared__ int sm[512];
    int t = threadIdx.x;
    int own = (t < NB) ? g_bsum[t] : 0;
    sm[t] = own;
    __syncthreads();
    #pragma unroll
    for (int o = 1; o < 512; o <<= 1) {
        int v = (t >= o) ? sm[t - o] : 0;
        __syncthreads();
        sm[t] += v;
        __syncthreads();
    }
    if (t < NB) g_bbase[t] = sm[t] - own;   // exclusive base per block
    // zero pool buckets (2048 floats)
    for (int j = t; j < NBUCK * 16; j += 512) g_poolB[j] = 0.f;
    if (t == 0) g_off[Nn] = ET;
}

// local scan + write offsets + fused self-loop placement
__global__ void k_scan3() {
    __shared__ int sm[256];
    int t = threadIdx.x;
    int i = blockIdx.x * 256 + t;
    int v = (i < Nn) ? g_cur[i] + 1 : 0;
    sm[t] = v;
    __syncthreads();
    #pragma unroll
    for (int o = 1; o < 256; o <<= 1) {
        int u = (t >= o) ? sm[t - o] : 0;
        __syncthreads();
        sm[t] += u;
        __syncthreads();
    }
    int off = g_bbase[blockIdx.x] + sm[t] - v;  // exclusive
    if (i < Nn) {
        g_off[i] = off;
        g_csr[off] = i;          // self loop first
        g_cur[i] = off + 1;      // cursor after self loop
    }
}

__global__ void k_scatter(const int4* __restrict__ src4, const int4* __restrict__ dst4) {
    int e = blockIdx.x * blockDim.x + threadIdx.x;
    int4 s = __ldg(&src4[e]);
    int4 d = __ldg(&dst4[e]);
    int p;
    p = atomicAdd(&g_cur[d.x], 1); g_csr[p] = s.x;
    p = atomicAdd(&g_cur[d.y], 1); g_csr[p] = s.y;
    p = atomicAdd(&g_cur[d.z], 1); g_csr[p] = s.z;
    p = atomicAdd(&g_cur[d.w], 1); g_csr[p] = s.w;
}

// -------- Layer 1 (rank-1 GAT) + node-local layer-2 projection --------
// Warp per node. Produces g_h2 (h2pre), g_as2/g_ad2. Also re-zeroes g_cur.
__global__ void k_layer1(const float* __restrict__ x,
                         const float* __restrict__ W1, const float* __restrict__ as1,
                         const float* __restrict__ ad1, const float* __restrict__ b1,
                         const float* __restrict__ W2, const float* __restrict__ as2,
                         const float* __restrict__ ad2) {
    __shared__ float W1s[64], b1s[64], W2s[1024], s1s[4], d1s[4], as2s[16], ad2s[16];
    int tid = threadIdx.x;
    if (tid < 64) { W1s[tid] = W1[tid]; b1s[tid] = b1[tid]; }
    for (int j = tid; j < 1024; j += blockDim.x) W2s[j] = W2[j];
    if (tid < 16) { as2s[tid] = as2[tid]; ad2s[tid] = ad2[tid]; }
    if (tid < 8) {
        int h = tid & 3;
        const float* a = (tid < 4) ? as1 : ad1;
        float s = 0.f;
        #pragma unroll
        for (int c = 0; c < 16; c++) s += W1[h * 16 + c] * a[h * 16 + c];
        if (tid < 4) s1s[h] = s; else d1s[h] = s;
    }
    __syncthreads();

    int i = blockIdx.x * (blockDim.x >> 5) + (tid >> 5);
    if (i >= Nn) return;
    int lane = tid & 31;
    if (lane == 0) g_cur[i] = 0;   // restore invariant for next call

    float xi = x[i];
    int lo = g_off[i], hi = g_off[i + 1];
    float s10 = s1s[0], s11 = s1s[1], s12 = s1s[2], s13 = s1s[3];
    float xd0 = xi * d1s[0], xd1 = xi * d1s[1], xd2 = xi * d1s[2], xd3 = xi * d1s[3];
    float n0 = 0.f, n1 = 0.f, n2 = 0.f, n3 = 0.f;
    float d0 = 0.f, d1v = 0.f, d2 = 0.f, d3 = 0.f;

    for (int p = lo + lane; p < hi; p += 32) {
        int s = __ldg(&g_csr[p]);
        float xs = __ldg(&x[s]);
        float e0 = xs * s10 + xd0; e0 = e0 > 0.f ? e0 : 0.2f * e0; float w0 = __expf(e0);
        float e1 = xs * s11 + xd1; e1 = e1 > 0.f ? e1 : 0.2f * e1; float w1 = __expf(e1);
        float e2 = xs * s12 + xd2; e2 = e2 > 0.f ? e2 : 0.2f * e2; float w2 = __expf(e2);
        float e3 = xs * s13 + xd3; e3 = e3 > 0.f ? e3 : 0.2f * e3; float w3 = __expf(e3);
        d0 += w0; d1v += w1; d2 += w2; d3 += w3;
        n0 = fmaf(w0, xs, n0); n1 = fmaf(w1, xs, n1);
        n2 = fmaf(w2, xs, n2); n3 = fmaf(w3, xs, n3);
    }
    #pragma unroll
    for (int o = 16; o > 0; o >>= 1) {
        n0 += __shfl_xor_sync(~0u, n0, o); n1 += __shfl_xor_sync(~0u, n1, o);
        n2 += __shfl_xor_sync(~0u, n2, o); n3 += __shfl_xor_sync(~0u, n3, o);
        d0 += __shfl_xor_sync(~0u, d0, o); d1v += __shfl_xor_sync(~0u, d1v, o);
        d2 += __shfl_xor_sync(~0u, d2, o); d3 += __shfl_xor_sync(~0u, d3, o);
    }
    float S0 = n0 / (d0 + 1e-16f), S1 = n1 / (d1v + 1e-16f);
    float S2 = n2 / (d2 + 1e-16f), S3 = n3 / (d3 + 1e-16f);

    // h2pre[c] = sum_j relu(W1[j]*S[j>>4] + b1[j]) * W2[j][c]
    int c = lane & 15;
    int jb = (lane >> 4) * 32;
    float SA = (lane < 16) ? S0 : S2;
    float SB = (lane < 16) ? S1 : S3;
    float acc = 0.f;
    #pragma unroll
    for (int jj = 0; jj < 32; jj++) {
        float Sv = (jj < 16) ? SA : SB;
        int j = jb + jj;
        float o1 = fmaf(W1s[j], Sv, b1s[j]);
        o1 = o1 > 0.f ? o1 : 0.f;
        acc = fmaf(o1, W2s[j * 16 + c], acc);
    }
    acc += __shfl_xor_sync(~0u, acc, 16);

    if (lane < 16) g_h2[i * 16 + lane] = acc;

    float ps = acc * as2s[c], pd = acc * ad2s[c];
    #pragma unroll
    for (int o = 4; o > 0; o >>= 1) {
        ps += __shfl_xor_sync(~0u, ps, o);
        pd += __shfl_xor_sync(~0u, pd, o);
    }
    float ps0 = __shfl_sync(~0u, ps, 0), ps1 = __shfl_sync(~0u, ps, 8);
    float pd0 = __shfl_sync(~0u, pd, 0), pd1 = __shfl_sync(~0u, pd, 8);
    if (lane == 0) {
        g_as2[i] = make_float2(ps0, ps1);
        g_ad2[i] = make_float2(pd0, pd1);
    }
}

// -------- Layer 2: warp per node, QUAD (4 lanes) per edge --------
// Each quad's 4 lanes load the 4 consecutive float4s of one node's 64B h2 row
// (same 128B line -> ~1 L1 wavefront per edge instead of 4).
// Channel quarter = lane&3; quarters 0,1 use head-0 weight, 2,3 head-1.
__global__ void k_layer2(const float* __restrict__ b2) {
    __shared__ float pool_s[16];
    int tid = threadIdx.x;
    if (tid < 16) pool_s[tid] = 0.f;
    __syncthreads();

    int i = blockIdx.x * (blockDim.x >> 5) + (tid >> 5);
    int lane = tid & 31;
    int sub = lane & 3;      // channel quarter
    int q   = lane >> 2;     // edge slot within warp (0..7)

    if (i < Nn) {
        float2 ad = g_ad2[i];
        float adv = (sub < 2) ? ad.x : ad.y;
        int lo = g_off[i], hi = g_off[i + 1];
        float4 acc = make_float4(0.f, 0.f, 0.f, 0.f);
        float den = 0.f;

        for (int p = lo + q; p < hi; p += 8) {
            int s = __ldg(&g_csr[p]);
            float2 as = __ldg(&g_as2[s]);
            float e = ((sub < 2) ? as.x : as.y) + adv;
            e = e > 0.f ? e : 0.2f * e;
            float w = __expf(e);
            den += w;
            float4 v = __ldg((const float4*)(g_h2 + s * 16) + sub);
            acc.x = fmaf(w, v.x, acc.x);
            acc.y = fmaf(w, v.y, acc.y);
            acc.z = fmaf(w, v.z, acc.z);
            acc.w = fmaf(w, v.w, acc.w);
        }
        // reduce across the 8 quads (sub stays fixed)
        #pragma unroll
        for (int o = 4; o < 32; o <<= 1) {
            acc.x += __shfl_xor_sync(~0u, acc.x, o);
            acc.y += __shfl_xor_sync(~0u, acc.y, o);
            acc.z += __shfl_xor_sync(~0u, acc.z, o);
            acc.w += __shfl_xor_sync(~0u, acc.w, o);
            den   += __shfl_xor_sync(~0u, den, o);
        }
        if (lane < 4) {                    // lane==sub here (q==0)
            float d = den + 1e-16f;
            int c0 = lane * 4;
            float v0 = acc.x / d + b2[c0 + 0]; v0 = v0 > 0.f ? v0 : 0.f;
            float v1 = acc.y / d + b2[c0 + 1]; v1 = v1 > 0.f ? v1 : 0.f;
            float v2 = acc.z / d + b2[c0 + 2]; v2 = v2 > 0.f ? v2 : 0.f;
            float v3 = acc.w / d + b2[c0 + 3]; v3 = v3 > 0.f ? v3 : 0.f;
            atomicAdd(&pool_s[c0 + 0], v0);
            atomicAdd(&pool_s[c0 + 1], v1);
            atomicAdd(&pool_s[c0 + 2], v2);
            atomicAdd(&pool_s[c0 + 3], v3);
        }
    }
    __syncthreads();
    if (tid < 16)
        atomicAdd(&g_poolB[(blockIdx.x & (NBUCK - 1)) * 16 + tid], pool_s[tid]);
}

// -------- MLP head + sigmoid, single warp --------
__global__ void k_head(const float* __restrict__ f1w, const float* __restrict__ f1b,
                       const float* __restrict__ f2w, const float* __restrict__ f2b,
                       float* __restrict__ out) {
    int lane = threadIdx.x;
    float pc = 0.f;
    if (lane < 16) {
        #pragma unroll 8
        for (int k = 0; k < NBUCK; k++) pc += g_poolB[k * 16 + lane];
    }
    const float invN = 1.f / (float)Nn;
    float z1 = f1b[lane];
    #pragma unroll
    for (int c = 0; c < 16; c++) {
        float v = __shfl_sync(~0u, pc, c);
        z1 = fmaf(v * invN, f1w[c * 32 + lane], z1);
    }
    z1 = z1 > 0.f ? z1 : 0.f;
    float z2 = (lane < 10) ? f2b[lane] : 0.f;
    #pragma unroll
    for (int k = 0; k < 32; k++) {
        float zk = __shfl_sync(~0u, z1, k);
        if (lane < 10) z2 = fmaf(zk, f2w[k * 10 + lane], z2);
    }
    if (lane < 10) out[lane] = 1.f / (1.f + __expf(-z2));
}

extern "C" void kernel_launch(void* const* d_in, const int* in_sizes, int n_in,
                              void* d_out, int out_size) {
    const float* x   = (const float*)d_in[0];
    const int*   ei  = (const int*)  d_in[1];
    const float* W1  = (const float*)d_in[2];
    const float* as1 = (const float*)d_in[3];
    const float* ad1 = (const float*)d_in[4];
    const float* b1  = (const float*)d_in[5];
    const float* W2  = (const float*)d_in[6];
    const float* as2 = (const float*)d_in[7];
    const float* ad2 = (const float*)d_in[8];
    const float* b2  = (const float*)d_in[9];
    const float* f1w = (const float*)d_in[10];
    const float* f1b = (const float*)d_in[11];
    const float* f2w = (const float*)d_in[12];
    const float* f2b = (const float*)d_in[13];

    const int4* src4 = (const int4*)ei;
    const int4* dst4 = (const int4*)(ei + Ee);

    k_hist   <<<Ee / 4 / 256, 256>>>(dst4);
    k_scan1  <<<NB, 256>>>();
    k_scan2  <<<1, 512>>>();
    k_scan3  <<<NB, 256>>>();
    k_scatter<<<Ee / 4 / 256, 256>>>(src4, dst4);
    k_layer1 <<<(Nn + 7) / 8, 256>>>(x, W1, as1, ad1, b1, W2, as2, ad2);
    k_layer2 <<<(Nn + 7) / 8, 256>>>(b2);
    k_head   <<<1, 32>>>(f1w, f1b, f2w, f2b, (float*)d_out);
}